// round 15
// baseline (speedup 1.0000x reference)
#include <cuda_runtime.h>
#include <cuda_bf16.h>
#include <cstdint>

// Problem constants
#define B 8
#define S 2048
#define DIN 768
#define DH 64
#define NROWS (B*S)      // 16384
#define KSPLIT 2
#define KEYS_PER_SPLIT (S/KSPLIT)   // 1024
#define NT (KEYS_PER_SPLIT/64)      // 16 tiles per CTA

// q/k: pure bf16 (hi only), pure-bf16 GEMM (score noise ~3e-5, validated).
// q rows pre-scaled by 0.125*log2(e) -> QK MMA yields log2-domain scores.
// v: bf16 hi/lo computed bf16x3 (v errors propagate directly).
// Attention: p = 1 + f decomposition, O = Sum(v) + Sum(f*vh), f = 2^s - 1.
__device__ __nv_bfloat16 g_qh[NROWS*DH];                   // [b*S+s][d]
__device__ __nv_bfloat16 g_kh[NROWS*DH];                   // [b*S+s][d]
__device__ __nv_bfloat16 g_vh[B*DH*S],  g_vl[B*DH*S];      // TRANSPOSED [b][d][s]
__device__ __nv_bfloat16 g_wth[3*DH*DIN], g_wtl[3*DH*DIN]; // [which][n][k] hi/lo
__device__ float g_vsum[B*DH];
__device__ float g_opart[KSPLIT*NROWS*DH];   // 8.4 MB
__device__ float g_lpart[KSPLIT*NROWS];

#define LOG2E 1.4426950408889634f

__device__ __forceinline__ uint32_t smem_u32(const void* p) {
    uint32_t a;
    asm("{ .reg .u64 t; cvta.to.shared.u64 t, %1; cvt.u32.u64 %0, t; }" : "=r"(a) : "l"(p));
    return a;
}

// ---- base-PTX tensor core / async ops (sm_80+, compile for plain sm_103) ----
__device__ __forceinline__ void ldsm_x4(uint32_t &r0, uint32_t &r1, uint32_t &r2, uint32_t &r3,
                                        uint32_t addr) {
    asm volatile("ldmatrix.sync.aligned.m8n8.x4.shared.b16 {%0,%1,%2,%3}, [%4];"
                 : "=r"(r0), "=r"(r1), "=r"(r2), "=r"(r3) : "r"(addr));
}
__device__ __forceinline__ void mma16816(float* c, const uint32_t* a, uint32_t b0, uint32_t b1) {
    asm volatile("mma.sync.aligned.m16n8k16.row.col.f32.bf16.bf16.f32 "
                 "{%0,%1,%2,%3}, {%4,%5,%6,%7}, {%8,%9}, {%0,%1,%2,%3};"
                 : "+f"(c[0]), "+f"(c[1]), "+f"(c[2]), "+f"(c[3])
                 : "r"(a[0]), "r"(a[1]), "r"(a[2]), "r"(a[3]), "r"(b0), "r"(b1));
}
__device__ __forceinline__ void cpa16(uint32_t dst, const void* src) {
    asm volatile("cp.async.cg.shared.global [%0], [%1], 16;" :: "r"(dst), "l"(src));
}
#define CP_COMMIT() asm volatile("cp.async.commit_group;" ::: "memory")
#define CP_WAIT0()  asm volatile("cp.async.wait_group 0;" ::: "memory")

__device__ __forceinline__ float ex2f(float x) {
    float r; asm("ex2.approx.f32 %0, %1;" : "=f"(r) : "f"(x)); return r;
}
__device__ __forceinline__ uint32_t bf2_pack(float a, float b) {
    uint32_t r;
    asm("cvt.rn.bf16x2.f32 %0, %1, %2;" : "=r"(r) : "f"(b), "f"(a));
    return r;
}
__device__ __forceinline__ void split2(float a, float b, uint32_t &hp, uint32_t &lp) {
    __nv_bfloat16 ha = __float2bfloat16(a), hb = __float2bfloat16(b);
    float la = a - __bfloat162float(ha), lb = b - __bfloat162float(hb);
    __nv_bfloat162 hh = __halves2bfloat162(ha, hb);
    hp = *(uint32_t*)&hh;
    lp = bf2_pack(la, lb);
}

// ============================================================
// prep_w: transpose + bf16 hi/lo split of the 3 weight matrices once.
// Block 0 also zeroes g_vsum (accumulated by proj's v epilogue via atomics).
// ============================================================
__global__ __launch_bounds__(256) void prep_w(
    const float* __restrict__ Wq, const float* __restrict__ Wk, const float* __restrict__ Wv)
{
    if (blockIdx.x == 0) {
        g_vsum[threadIdx.x] = 0.f;
        g_vsum[threadIdx.x + 256] = 0.f;
    }
    int idx = blockIdx.x * 256 + threadIdx.x;
    int which = idx / (DIN*DH);
    int rem = idx - which * (DIN*DH);
    int k = rem >> 6;
    int n = rem & 63;
    const float* W = (which == 0) ? Wq : (which == 1) ? Wk : Wv;
    float w = W[(size_t)k*DH + n];
    __nv_bfloat16 h = __float2bfloat16(w);
    __nv_bfloat16 l = __float2bfloat16(w - __bfloat162float(h));
    size_t o = ((size_t)which*DH + n)*DIN + k;
    g_wth[o] = h;
    g_wtl[o] = l;
}

// ============================================================
// Projection, double-buffered cp.async pipeline, TWO paths:
//  q/k (which<2): PURE bf16, 128-k chunks (6 syncs, 128 MMAs/chunk) --
//                 deep per-sync compute hides the X LDG latency.
//  v   (which=2): bf16x3, 64-k chunks (12 syncs, 192 MMAs/chunk);
//                 epilogue accumulates exact column sums (vsum).
// ============================================================
#define PP 72        // v-path pitch (64-k chunk)
#define PP2 136      // qk-path pitch (128-k chunk)
#define TP 136
#define NCHUNK_V (DIN/64)            // 12
#define NCHUNK_QK (DIN/128)          // 6
#define SH_V (2*128*PP + 2*64*PP)    // v stage halves
#define SH_QK (128*PP2 + 64*PP2)     // qk stage halves (26112 < 27648)
#define PROJ_SMEM (2 * SH_V * 2)     // 110592 B

__global__ __launch_bounds__(256, 2) void proj_kernel(
    const float* __restrict__ Xq, const float* __restrict__ Xk, const float* __restrict__ Xv,
    const float* __restrict__ bq, const float* __restrict__ bk, const float* __restrict__ bv)
{
    extern __shared__ __nv_bfloat16 psm[];

    const int which = blockIdx.y;
    const float* X; const float* bias;
    if (which == 0)      { X = Xq; bias = bq; }
    else if (which == 1) { X = Xk; bias = bk; }
    else                 { X = Xv; bias = bv; }
    const __nv_bfloat16* wth = g_wth + (size_t)which*DH*DIN;
    const __nv_bfloat16* wtl = g_wtl + (size_t)which*DH*DIN;

    const int tid = threadIdx.x;
    const int warp = tid >> 5;
    const int lane = tid & 31;
    const int rowblock = blockIdx.x * 128;

    float cacc[8][4];
    #pragma unroll
    for (int j = 0; j < 8; j++)
        #pragma unroll
        for (int i = 0; i < 4; i++) cacc[j][i] = 0.f;

    const int arow = warp*16 + (lane & 15);
    const int acol = (lane >> 4) * 8;
    const int brow = (lane & 7) | ((lane & 16) >> 1);
    const int bcol = (lane & 8);

    if (which < 2) {
        // ======== q/k path: pure bf16, 128-k chunks ========
        const int rb  = tid >> 5;        // row base 0..7 (rows rb + 8i)
        const int c4  = tid & 31;        // float4 col within 128-k chunk
        float4 xr[16];

        // prologue: chunk 0 LDG -> stage0; W0 cp.async; chunk 1 LDG
        #pragma unroll
        for (int i = 0; i < 16; i++)
            xr[i] = *(const float4*)(X + (size_t)(rowblock + rb + i*8)*DIN + c4*4);
        {
            __nv_bfloat16* sXh = psm;
            uint32_t whb = smem_u32(psm + 128*PP2);
            #pragma unroll
            for (int i = 0; i < 16; i++) {
                int r = rb + i*8;
                *(uint2*)&sXh[r*PP2 + c4*4] =
                    make_uint2(bf2_pack(xr[i].x, xr[i].y), bf2_pack(xr[i].z, xr[i].w));
            }
            #pragma unroll
            for (int i = 0; i < 4; i++) {
                int idx = tid + i*256;
                int n = idx >> 4, c = idx & 15;
                cpa16(whb + (uint32_t)(n*PP2 + c*8)*2, wth + (size_t)n*DIN + c*8);
            }
            CP_COMMIT();
        }
        #pragma unroll
        for (int i = 0; i < 16; i++)
            xr[i] = *(const float4*)(X + (size_t)(rowblock + rb + i*8)*DIN + 128 + c4*4);
        CP_WAIT0();
        __syncthreads();

        for (int c = 0; c < NCHUNK_QK; c++) {
            __nv_bfloat16* cur = psm + (c & 1) * SH_QK;
            __nv_bfloat16* nxt = psm + ((c + 1) & 1) * SH_QK;

            if (c + 1 < NCHUNK_QK) {
                __nv_bfloat16* nXh = nxt;
                uint32_t nwb = smem_u32(nxt + 128*PP2);
                const int kn = (c + 1) * 128;
                #pragma unroll
                for (int i = 0; i < 16; i++) {
                    int r = rb + i*8;
                    *(uint2*)&nXh[r*PP2 + c4*4] =
                        make_uint2(bf2_pack(xr[i].x, xr[i].y), bf2_pack(xr[i].z, xr[i].w));
                }
                #pragma unroll
                for (int i = 0; i < 4; i++) {
                    int idx = tid + i*256;
                    int n = idx >> 4, cc8 = idx & 15;
                    cpa16(nwb + (uint32_t)(n*PP2 + cc8*8)*2, wth + (size_t)n*DIN + kn + cc8*8);
                }
                CP_COMMIT();
            }
            if (c + 2 < NCHUNK_QK) {
                const int kf = (c + 2) * 128;
                #pragma unroll
                for (int i = 0; i < 16; i++)
                    xr[i] = *(const float4*)(X + (size_t)(rowblock + rb + i*8)*DIN + kf + c4*4);
            }

            __nv_bfloat16* cXh = cur;
            __nv_bfloat16* cWh = cur + 128*PP2;
            #pragma unroll
            for (int ks = 0; ks < 8; ks++) {
                uint32_t afh[4];
                ldsm_x4(afh[0], afh[1], afh[2], afh[3], smem_u32(&cXh[arow*PP2 + ks*16 + acol]));
                #pragma unroll
                for (int jj = 0; jj < 8; jj += 2) {
                    uint32_t bh0,bh1,bh2,bh3;
                    ldsm_x4(bh0,bh1,bh2,bh3, smem_u32(&cWh[(jj*8 + brow)*PP2 + ks*16 + bcol]));
                    mma16816(cacc[jj],   afh, bh0, bh1);
                    mma16816(cacc[jj+1], afh, bh2, bh3);
                }
            }
            CP_WAIT0();
            __syncthreads();
        }
    } else {
        // ======== v path: bf16x3, 64-k chunks ========
        const int xr_ = tid >> 4;
        const int xc4 = tid & 15;
        float4 xr[8];

        #pragma unroll
        for (int i = 0; i < 8; i++)
            xr[i] = *(const float4*)(X + (size_t)(rowblock + xr_ + i*16)*DIN + xc4*4);
        {
            __nv_bfloat16* sXh = psm;
            __nv_bfloat16* sXl = sXh + 128*PP;
            uint32_t whb = smem_u32(sXl + 128*PP);
            #pragma unroll
            for (int i = 0; i < 8; i++) {
                int r = xr_ + i*16;
                uint32_t h0, l0, h1, l1;
                split2(xr[i].x, xr[i].y, h0, l0);
                split2(xr[i].z, xr[i].w, h1, l1);
                *(uint2*)&sXh[r*PP + xc4*4] = make_uint2(h0, h1);
                *(uint2*)&sXl[r*PP + xc4*4] = make_uint2(l0, l1);
            }
            #pragma unroll
            for (int i = 0; i < 2; i++) {
                int idx = tid + i*256;
                int n = idx >> 3, c = idx & 7;
                cpa16(whb + (uint32_t)(n*PP + c*8)*2, wth + (size_t)n*DIN + c*8);
                cpa16(whb + (uint32_t)(64*PP + n*PP + c*8)*2, wtl + (size_t)n*DIN + c*8);
            }
            CP_COMMIT();
        }
        #pragma unroll
        for (int i = 0; i < 8; i++)
            xr[i] = *(const float4*)(X + (size_t)(rowblock + xr_ + i*16)*DIN + 64 + xc4*4);
        CP_WAIT0();
        __syncthreads();

        for (int c = 0; c < NCHUNK_V; c++) {
            __nv_bfloat16* cur = psm + (c & 1) * SH_V;
            __nv_bfloat16* nxt = psm + ((c + 1) & 1) * SH_V;

            if (c + 1 < NCHUNK_V) {
                __nv_bfloat16* nXh = nxt;
                __nv_bfloat16* nXl = nXh + 128*PP;
                uint32_t nwb = smem_u32(nXl + 128*PP);
                const int kn = (c + 1) * 64;
                #pragma unroll
                for (int i = 0; i < 8; i++) {
                    int r = xr_ + i*16;
                    uint32_t h0, l0, h1, l1;
                    split2(xr[i].x, xr[i].y, h0, l0);
                    split2(xr[i].z, xr[i].w, h1, l1);
                    *(uint2*)&nXh[r*PP + xc4*4] = make_uint2(h0, h1);
                    *(uint2*)&nXl[r*PP + xc4*4] = make_uint2(l0, l1);
                }
                #pragma unroll
                for (int i = 0; i < 2; i++) {
                    int idx = tid + i*256;
                    int n = idx >> 3, cc8 = idx & 7;
                    cpa16(nwb + (uint32_t)(n*PP + cc8*8)*2, wth + (size_t)n*DIN + kn + cc8*8);
                    cpa16(nwb + (uint32_t)(64*PP + n*PP + cc8*8)*2,
                          wtl + (size_t)n*DIN + kn + cc8*8);
                }
                CP_COMMIT();
            }
            if (c + 2 < NCHUNK_V) {
                const int kf = (c + 2) * 64;
                #pragma unroll
                for (int i = 0; i < 8; i++)
                    xr[i] = *(const float4*)(X + (size_t)(rowblock + xr_ + i*16)*DIN + kf + xc4*4);
            }

            __nv_bfloat16* cXh = cur;
            __nv_bfloat16* cXl = cXh + 128*PP;
            __nv_bfloat16* cWh = cXl + 128*PP;
            __nv_bfloat16* cWl = cWh + 64*PP;
            #pragma unroll
            for (int ks = 0; ks < 4; ks++) {
                uint32_t afh[4], afl[4];
                ldsm_x4(afh[0], afh[1], afh[2], afh[3], smem_u32(&cXh[arow*PP + ks*16 + acol]));
                ldsm_x4(afl[0], afl[1], afl[2], afl[3], smem_u32(&cXl[arow*PP + ks*16 + acol]));
                #pragma unroll
                for (int jj = 0; jj < 8; jj += 2) {
                    uint32_t bh0,bh1,bh2,bh3, bl0,bl1,bl2,bl3;
                    ldsm_x4(bh0,bh1,bh2,bh3, smem_u32(&cWh[(jj*8 + brow)*PP + ks*16 + bcol]));
                    ldsm_x4(bl0,bl1,bl2,bl3, smem_u32(&cWl[(jj*8 + brow)*PP + ks*16 + bcol]));
                    mma16816(cacc[jj],   afh, bh0, bh1);
                    mma16816(cacc[jj],   afh, bl0, bl1);
                    mma16816(cacc[jj],   afl, bh0, bh1);
                    mma16816(cacc[jj+1], afh, bh2, bh3);
                    mma16816(cacc[jj+1], afh, bl2, bl3);
                    mma16816(cacc[jj+1], afl, bh2, bh3);
                }
            }
            CP_WAIT0();
            __syncthreads();
        }
    }

    // ---- epilogue ----
    const int cc = (lane & 3) * 2;
    #pragma unroll
    for (int j = 0; j < 8; j++) {
        float b0 = bias[j*8 + cc], b1 = bias[j*8 + cc + 1];
        cacc[j][0] += b0; cacc[j][1] += b1;
        cacc[j][2] += b0; cacc[j][3] += b1;
    }

    if (which < 2) {
        float ss0 = 0.f, ss1 = 0.f;
        #pragma unroll
        for (int j = 0; j < 8; j++) {
            ss0 += cacc[j][0]*cacc[j][0] + cacc[j][1]*cacc[j][1];
            ss1 += cacc[j][2]*cacc[j][2] + cacc[j][3]*cacc[j][3];
        }
        ss0 += __shfl_xor_sync(0xffffffffu, ss0, 1);
        ss0 += __shfl_xor_sync(0xffffffffu, ss0, 2);
        ss1 += __shfl_xor_sync(0xffffffffu, ss1, 1);
        ss1 += __shfl_xor_sync(0xffffffffu, ss1, 2);
        float sc0 = rsqrtf(ss0), sc1 = rsqrtf(ss1);
        if (which == 0) { sc0 *= 0.125f * LOG2E; sc1 *= 0.125f * LOG2E; }

        __nv_bfloat16* gh = (which == 0) ? g_qh : g_kh;
        const int r0 = rowblock + warp*16 + (lane >> 2);
        const int r1 = r0 + 8;
        #pragma unroll
        for (int j = 0; j < 8; j++) {
            *(uint32_t*)&gh[(size_t)r0*DH + j*8 + cc] = bf2_pack(cacc[j][0]*sc0, cacc[j][1]*sc0);
            *(uint32_t*)&gh[(size_t)r1*DH + j*8 + cc] = bf2_pack(cacc[j][2]*sc1, cacc[j][3]*sc1);
        }
    } else {
        __nv_bfloat16* Th = psm;        // 64 x TP
        __nv_bfloat16* Tl = Th + 64*TP;
        const int r0 = warp*16 + (lane >> 2);
        const int r1 = r0 + 8;
        #pragma unroll
        for (int j = 0; j < 8; j++) {
            #pragma unroll
            for (int e = 0; e < 2; e++) {
                int col = j*8 + cc + e;
                float v0 = cacc[j][e], v1 = cacc[j][2+e];
                __nv_bfloat16 h0 = __float2bfloat16(v0);
                __nv_bfloat16 h1 = __float2bfloat16(v1);
                Th[col*TP + r0] = h0;
                Th[col*TP + r1] = h1;
                Tl[col*TP + r0] = __float2bfloat16(v0 - __bfloat162float(h0));
                Tl[col*TP + r1] = __float2bfloat16(v1 - __bfloat162float(h1));
            }
        }
        __syncthreads();
        const int bb = rowblock >> 11;
        const int s0 = rowblock & (S - 1);
        #pragma unroll
        for (int i = 0; i < 4; i++) {
            int idx = tid + i*256;
            int col = idx >> 4, u = idx & 15;
            size_t g = ((size_t)bb*DH + col)*S + s0 + u*8;
            *(uint4*)&g_vh[g] = *(uint4*)&Th[col*TP + u*8];
            *(uint4*)&g_vl[g] = *(uint4*)&Tl[col*TP + u*8];
        }
        // fused vsum: partial column sums of this 128-row tile (hi+lo), atomic.
        {
            int col = tid & 63, seg = tid >> 6;
            float s = 0.f;
            #pragma unroll 8
            for (int r = seg*32; r < seg*32 + 32; r++)
                s += __bfloat162float(Th[col*TP + r]) + __bfloat162float(Tl[col*TP + r]);
            atomicAdd(&g_vsum[bb*DH + col], s);
        }
    }
}

// ============================================================
// mma.sync flash attention, split-K x2, p = 1+f decomposition,
// cp.async double-buffered K/V. Q smem aliased with V buffer 1 -> 36864 B,
// 5 CTAs/SM.
// ============================================================
#define TPITCH 72
#define RB 9216
#define ATTN_SMEM (4 * RB)             // 36864 B

__global__ __launch_bounds__(128, 5) void attn_part_kernel()
{
    extern __shared__ __nv_bfloat16 AS[];

    const int tid = threadIdx.x;
    const int warp = tid >> 5;
    const int lane = tid & 31;
    const int b = blockIdx.y;
    const int q0 = blockIdx.x * 64;
    const int split = blockIdx.z;
    const int key_base = split * KEYS_PER_SPLIT;

    const uint32_t sbase = smem_u32(AS);
    const uint32_t KB[2] = { sbase,        sbase + 2*RB };
    const uint32_t VB[2] = { sbase + RB,   sbase + 3*RB };
    const uint32_t QB = sbase + 3*RB;    // aliases VB[1]; Q consumed before t=0 prefetch

    const __nv_bfloat16* qh_g = g_qh + ((size_t)b*S + q0)*DH;
    const __nv_bfloat16* kh_g = g_kh + (size_t)b*S*DH;
    const __nv_bfloat16* vh_g = g_vh + (size_t)b*DH*S;

    const int sr = tid >> 3;
    const int sc = tid & 7;

    #pragma unroll
    for (int i = 0; i < 4; i++) {
        int r = sr + i*16;
        uint32_t so = (uint32_t)(r*TPITCH + sc*8)*2;
        cpa16(QB + so, qh_g + (size_t)r*DH + sc*8);
        cpa16(KB[0] + so, kh_g + (size_t)(key_base + r)*DH + sc*8);
        cpa16(VB[0] + so, vh_g + (size_t)r*S + key_base + sc*8);
    }
    CP_COMMIT();
    CP_WAIT0();
    __syncthreads();

    const int arow = warp*16 + (lane & 15);
    const int acol = (lane >> 4) * 8;
    const int brow = (lane & 7) | ((lane & 16) >> 1);
    const int bcol = (lane & 8);

    uint32_t qfh[4][4];
    #pragma unroll
    for (int k = 0; k < 4; k++)
        ldsm_x4(qfh[k][0], qfh[k][1], qfh[k][2], qfh[k][3],
                QB + (uint32_t)(arow*TPITCH + k*16 + acol)*2);
    __syncthreads();   // all warps done reading Q before t=0 prefetch reuses QB

    float oacc[8][4];
    #pragma unroll
    for (int j = 0; j < 8; j++)
        #pragma unroll
        for (int i = 0; i < 4; i++) oacc[j][i] = 0.f;
    float lsum0 = 0.f, lsum1 = 0.f;

    for (int t = 0; t < NT; t++) {
        const uint32_t kb = KB[t & 1], vb = VB[t & 1];

        if (t + 1 < NT) {
            const int kn = key_base + (t + 1) * 64;
            const uint32_t nk = KB[(t + 1) & 1], nv = VB[(t + 1) & 1];
            #pragma unroll
            for (int i = 0; i < 4; i++) {
                int r = sr + i*16;
                uint32_t so = (uint32_t)(r*TPITCH + sc*8)*2;
                cpa16(nk + so, kh_g + (size_t)(kn + r)*DH + sc*8);
                cpa16(nv + so, vh_g + (size_t)r*S + kn + sc*8);
            }
            CP_COMMIT();
        }

        float sacc[8][4];
        #pragma unroll
        for (int j = 0; j < 8; j++)
            #pragma unroll
            for (int i = 0; i < 4; i++) sacc[j][i] = 0.f;

        #pragma unroll
        for (int k = 0; k < 4; k++) {
            #pragma unroll
            for (int jj = 0; jj < 8; jj += 2) {
                uint32_t bh0,bh1,bh2,bh3;
                ldsm_x4(bh0,bh1,bh2,bh3, kb + (uint32_t)((jj*8 + brow)*TPITCH + k*16 + bcol)*2);
                mma16816(sacc[jj],   qfh[k], bh0, bh1);
                mma16816(sacc[jj+1], qfh[k], bh2, bh3);
            }
        }

        #pragma unroll
        for (int kk = 0; kk < 4; kk++) {
            uint32_t pf[4];
            {
                float f0 = ex2f(sacc[2*kk][0])   - 1.0f;
                float f1 = ex2f(sacc[2*kk][1])   - 1.0f;
                float f2 = ex2f(sacc[2*kk][2])   - 1.0f;
                float f3 = ex2f(sacc[2*kk][3])   - 1.0f;
                float f4 = ex2f(sacc[2*kk+1][0]) - 1.0f;
                float f5 = ex2f(sacc[2*kk+1][1]) - 1.0f;
                float f6 = ex2f(sacc[2*kk+1][2]) - 1.0f;
                float f7 = ex2f(sacc[2*kk+1][3]) - 1.0f;
                lsum0 += f0 + f1 + f4 + f5;
                lsum1 += f2 + f3 + f6 + f7;
                pf[0] = bf2_pack(f0, f1);
                pf[1] = bf2_pack(f2, f3);
                pf[2] = bf2_pack(f4, f5);
                pf[3] = bf2_pack(f6, f7);
            }
            #pragma unroll
            for (int jj = 0; jj < 8; jj += 2) {
                uint32_t vh0,vh1,vh2,vh3;
                ldsm_x4(vh0,vh1,vh2,vh3, vb + (uint32_t)((jj*8 + brow)*TPITCH + kk*16 + bcol)*2);
                mma16816(oacc[jj],   pf, vh0, vh1);
                mma16816(oacc[jj+1], pf, vh2, vh3);
            }
        }

        if (t + 1 < NT) {
            CP_WAIT0();
            __syncthreads();
        }
    }

    lsum0 += __shfl_xor_sync(0xffffffffu, lsum0, 1);
    lsum0 += __shfl_xor_sync(0xffffffffu, lsum0, 2);
    lsum1 += __shfl_xor_sync(0xffffffffu, lsum1, 1);
    lsum1 += __shfl_xor_sync(0xffffffffu, lsum1, 2);

    const size_t grow = (size_t)b*S + q0 + warp*16 + (lane >> 2);
    const int cc = (lane & 3) * 2;
    float* o0 = g_opart + ((size_t)split*NROWS + grow)*DH + cc;
    float* o1 = o0 + 8*DH;
    #pragma unroll
    for (int j = 0; j < 8; j++) {
        *(float2*)(o0 + j*8) = make_float2(oacc[j][0], oacc[j][1]);
        *(float2*)(o1 + j*8) = make_float2(oacc[j][2], oacc[j][3]);
    }
    if ((lane & 3) == 0) {
        g_lpart[(size_t)split*NROWS + grow]     = lsum0;
        g_lpart[(size_t)split*NROWS + grow + 8] = lsum1;
    }
}

// ============================================================
// Combine: o = (vsum + Sum_splits f*vh) / (2048 + Sum_splits Sum f).
// ============================================================
__global__ __launch_bounds__(256) void attn_combine_kernel(float* __restrict__ out)
{
    const int id  = blockIdx.x * 256 + threadIdx.x;
    const int row = id >> 4;
    const int c   = id & 15;

    float4 acc = *(const float4*)&g_vsum[(row >> 11)*DH + c*4];
    float L = (float)S;
    #pragma unroll
    for (int s = 0; s < KSPLIT; s++) {
        const float4 v = ((const float4*)(g_opart + ((size_t)s*NROWS + row)*DH))[c];
        acc.x += v.x; acc.y += v.y; acc.z += v.z; acc.w += v.w;
        L += g_lpart[(size_t)s*NROWS + row];
    }
    const float inv = 1.0f / L;
    ((float4*)out)[id] = make_float4(acc.x*inv, acc.y*inv, acc.z*inv, acc.w*inv);
}

// ============================================================
extern "C" void kernel_launch(void* const* d_in, const int* in_sizes, int n_in,
                              void* d_out, int out_size)
{
    const float* query = (const float*)d_in[0];
    const float* key   = (const float*)d_in[1];
    const float* value = (const float*)d_in[2];
    const float* Wq    = (const float*)d_in[3];
    const float* bq    = (const float*)d_in[4];
    const float* Wk    = (const float*)d_in[5];
    const float* bk    = (const float*)d_in[6];
    const float* Wv    = (const float*)d_in[7];
    const float* bv    = (const float*)d_in[8];
    float* out = (float*)d_out;

    cudaFuncSetAttribute(proj_kernel,
                         cudaFuncAttributeMaxDynamicSharedMemorySize, PROJ_SMEM);
    cudaFuncSetAttribute(attn_part_kernel,
                         cudaFuncAttributeMaxDynamicSharedMemorySize, ATTN_SMEM);

    prep_w<<<3*DIN*DH/256, 256>>>(Wq, Wk, Wv);

    dim3 pgrid(NROWS / 128, 3);
    proj_kernel<<<pgrid, 256, PROJ_SMEM>>>(query, key, value, bq, bk, bv);

    dim3 agrid(S / 64, B, KSPLIT);    // 32 x 8 x 2 = 512 CTAs
    attn_part_kernel<<<agrid, 128, ATTN_SMEM>>>();

    attn_combine_kernel<<<NROWS * 16 / 256, 256>>>(out);
}

// round 16
// speedup vs baseline: 1.1372x; 1.1372x over previous
#include <cuda_runtime.h>
#include <cuda_bf16.h>
#include <cstdint>

// Problem constants
#define B 8
#define S 2048
#define DIN 768
#define DH 64
#define NROWS (B*S)      // 16384
#define KSPLIT 2
#define KEYS_PER_SPLIT (S/KSPLIT)   // 1024
#define NT (KEYS_PER_SPLIT/64)      // 16 tiles per CTA

// q/k: pure bf16 (hi only), pure-bf16 GEMM (score noise ~3e-5, validated).
// q rows pre-scaled by 0.125*log2(e) -> QK MMA yields log2-domain scores.
// v: bf16 hi/lo computed bf16x3 (v errors propagate directly).
// Attention: p = 1 + f decomposition, O = Sum(v) + Sum(f*vh), f = 2^s - 1.
__device__ __nv_bfloat16 g_qh[NROWS*DH];                   // [b*S+s][d]
__device__ __nv_bfloat16 g_kh[NROWS*DH];                   // [b*S+s][d]
__device__ __nv_bfloat16 g_vh[B*DH*S],  g_vl[B*DH*S];      // TRANSPOSED [b][d][s]
__device__ __nv_bfloat16 g_wth[3*DH*DIN], g_wtl[3*DH*DIN]; // [which][n][k] hi/lo
__device__ float g_vsum[B*DH];
__device__ float g_opart[KSPLIT*NROWS*DH];   // 8.4 MB
__device__ float g_lpart[KSPLIT*NROWS];

#define LOG2E 1.4426950408889634f

__device__ __forceinline__ uint32_t smem_u32(const void* p) {
    uint32_t a;
    asm("{ .reg .u64 t; cvta.to.shared.u64 t, %1; cvt.u32.u64 %0, t; }" : "=r"(a) : "l"(p));
    return a;
}

// ---- base-PTX tensor core / async ops (sm_80+, compile for plain sm_103) ----
__device__ __forceinline__ void ldsm_x4(uint32_t &r0, uint32_t &r1, uint32_t &r2, uint32_t &r3,
                                        uint32_t addr) {
    asm volatile("ldmatrix.sync.aligned.m8n8.x4.shared.b16 {%0,%1,%2,%3}, [%4];"
                 : "=r"(r0), "=r"(r1), "=r"(r2), "=r"(r3) : "r"(addr));
}
__device__ __forceinline__ void mma16816(float* c, const uint32_t* a, uint32_t b0, uint32_t b1) {
    asm volatile("mma.sync.aligned.m16n8k16.row.col.f32.bf16.bf16.f32 "
                 "{%0,%1,%2,%3}, {%4,%5,%6,%7}, {%8,%9}, {%0,%1,%2,%3};"
                 : "+f"(c[0]), "+f"(c[1]), "+f"(c[2]), "+f"(c[3])
                 : "r"(a[0]), "r"(a[1]), "r"(a[2]), "r"(a[3]), "r"(b0), "r"(b1));
}
__device__ __forceinline__ void cpa16(uint32_t dst, const void* src) {
    asm volatile("cp.async.cg.shared.global [%0], [%1], 16;" :: "r"(dst), "l"(src));
}
#define CP_COMMIT() asm volatile("cp.async.commit_group;" ::: "memory")
#define CP_WAIT0()  asm volatile("cp.async.wait_group 0;" ::: "memory")

__device__ __forceinline__ float ex2f(float x) {
    float r; asm("ex2.approx.f32 %0, %1;" : "=f"(r) : "f"(x)); return r;
}
__device__ __forceinline__ uint32_t bf2_pack(float a, float b) {
    uint32_t r;
    asm("cvt.rn.bf16x2.f32 %0, %1, %2;" : "=r"(r) : "f"(b), "f"(a));
    return r;
}
__device__ __forceinline__ void split2(float a, float b, uint32_t &hp, uint32_t &lp) {
    __nv_bfloat16 ha = __float2bfloat16(a), hb = __float2bfloat16(b);
    float la = a - __bfloat162float(ha), lb = b - __bfloat162float(hb);
    __nv_bfloat162 hh = __halves2bfloat162(ha, hb);
    hp = *(uint32_t*)&hh;
    lp = bf2_pack(la, lb);
}

// ============================================================
// prep_w: transpose + bf16 hi/lo split of the 3 weight matrices once.
// Block 0 also zeroes g_vsum (accumulated by proj's v epilogue via atomics).
// ============================================================
__global__ __launch_bounds__(256) void prep_w(
    const float* __restrict__ Wq, const float* __restrict__ Wk, const float* __restrict__ Wv)
{
    if (blockIdx.x == 0) {
        g_vsum[threadIdx.x] = 0.f;
        g_vsum[threadIdx.x + 256] = 0.f;
    }
    int idx = blockIdx.x * 256 + threadIdx.x;
    int which = idx / (DIN*DH);
    int rem = idx - which * (DIN*DH);
    int k = rem >> 6;
    int n = rem & 63;
    const float* W = (which == 0) ? Wq : (which == 1) ? Wk : Wv;
    float w = W[(size_t)k*DH + n];
    __nv_bfloat16 h = __float2bfloat16(w);
    __nv_bfloat16 l = __float2bfloat16(w - __bfloat162float(h));
    size_t o = ((size_t)which*DH + n)*DIN + k;
    g_wth[o] = h;
    g_wtl[o] = l;
}

// ============================================================
// Projection, double-buffered cp.async pipeline (R14 structure).
// WAVE ORDERING: blockIdx.y = 0 -> V (long, bf16x3), 1 -> Q, 2 -> K.
// The long v CTAs launch FIRST so they co-run with short q/k CTAs in
// wave 1 instead of forming a serialized second wave.
// q/k: pure bf16 (1 MMA/slot). v: bf16x3 + fused vsum.
// ============================================================
#define PP 72
#define TP 136
#define NCHUNK (DIN/64)                         // 12
#define STAGE_HALVES (2*128*PP + 2*64*PP)
#define PROJ_SMEM (2 * STAGE_HALVES * 2)        // 110592 B

__global__ __launch_bounds__(256, 2) void proj_kernel(
    const float* __restrict__ Xq, const float* __restrict__ Xk, const float* __restrict__ Xv,
    const float* __restrict__ bq, const float* __restrict__ bk, const float* __restrict__ bv)
{
    extern __shared__ __nv_bfloat16 psm[];

    // y=0 -> v (which=2), y=1 -> q (which=0), y=2 -> k (which=1)
    const int which = (blockIdx.y == 0) ? 2 : (int)blockIdx.y - 1;
    const bool lo = (which == 2);        // uniform per CTA
    const float* X; const float* bias;
    if (which == 0)      { X = Xq; bias = bq; }
    else if (which == 1) { X = Xk; bias = bk; }
    else                 { X = Xv; bias = bv; }
    const __nv_bfloat16* wth = g_wth + (size_t)which*DH*DIN;
    const __nv_bfloat16* wtl = g_wtl + (size_t)which*DH*DIN;

    const int tid = threadIdx.x;
    const int warp = tid >> 5;
    const int lane = tid & 31;
    const int rowblock = blockIdx.x * 128;

    float cacc[8][4];
    #pragma unroll
    for (int j = 0; j < 8; j++)
        #pragma unroll
        for (int i = 0; i < 4; i++) cacc[j][i] = 0.f;

    const int arow = warp*16 + (lane & 15);
    const int acol = (lane >> 4) * 8;
    const int brow = (lane & 7) | ((lane & 16) >> 1);
    const int bcol = (lane & 8);

    const int xr_ = tid >> 4;
    const int xc4 = tid & 15;
    float4 xr[8];

    // ---- prologue: chunk 0 stage + chunk 1 LDG ----
    #pragma unroll
    for (int i = 0; i < 8; i++)
        xr[i] = *(const float4*)(X + (size_t)(rowblock + xr_ + i*16)*DIN + xc4*4);
    {
        __nv_bfloat16* sXh = psm;
        __nv_bfloat16* sXl = sXh + 128*PP;
        uint32_t whb = smem_u32(sXl + 128*PP);
        #pragma unroll
        for (int i = 0; i < 8; i++) {
            int r = xr_ + i*16;
            if (lo) {
                uint32_t h0, l0, h1, l1;
                split2(xr[i].x, xr[i].y, h0, l0);
                split2(xr[i].z, xr[i].w, h1, l1);
                *(uint2*)&sXh[r*PP + xc4*4] = make_uint2(h0, h1);
                *(uint2*)&sXl[r*PP + xc4*4] = make_uint2(l0, l1);
            } else {
                *(uint2*)&sXh[r*PP + xc4*4] =
                    make_uint2(bf2_pack(xr[i].x, xr[i].y), bf2_pack(xr[i].z, xr[i].w));
            }
        }
        #pragma unroll
        for (int i = 0; i < 2; i++) {
            int idx = tid + i*256;
            int n = idx >> 3, c = idx & 7;
            cpa16(whb + (uint32_t)(n*PP + c*8)*2, wth + (size_t)n*DIN + c*8);
            if (lo) cpa16(whb + (uint32_t)(64*PP + n*PP + c*8)*2, wtl + (size_t)n*DIN + c*8);
        }
        CP_COMMIT();
    }
    #pragma unroll
    for (int i = 0; i < 8; i++)
        xr[i] = *(const float4*)(X + (size_t)(rowblock + xr_ + i*16)*DIN + 64 + xc4*4);
    CP_WAIT0();
    __syncthreads();

    // ---- main loop: one sync per chunk ----
    for (int c = 0; c < NCHUNK; c++) {
        __nv_bfloat16* cur = psm + (c & 1) * STAGE_HALVES;
        __nv_bfloat16* nxt = psm + ((c + 1) & 1) * STAGE_HALVES;

        if (c + 1 < NCHUNK) {
            __nv_bfloat16* nXh = nxt;
            __nv_bfloat16* nXl = nXh + 128*PP;
            uint32_t nwb = smem_u32(nXl + 128*PP);
            const int kn = (c + 1) * 64;
            #pragma unroll
            for (int i = 0; i < 8; i++) {
                int r = xr_ + i*16;
                if (lo) {
                    uint32_t h0, l0, h1, l1;
                    split2(xr[i].x, xr[i].y, h0, l0);
                    split2(xr[i].z, xr[i].w, h1, l1);
                    *(uint2*)&nXh[r*PP + xc4*4] = make_uint2(h0, h1);
                    *(uint2*)&nXl[r*PP + xc4*4] = make_uint2(l0, l1);
                } else {
                    *(uint2*)&nXh[r*PP + xc4*4] =
                        make_uint2(bf2_pack(xr[i].x, xr[i].y), bf2_pack(xr[i].z, xr[i].w));
                }
            }
            #pragma unroll
            for (int i = 0; i < 2; i++) {
                int idx = tid + i*256;
                int n = idx >> 3, cc8 = idx & 7;
                cpa16(nwb + (uint32_t)(n*PP + cc8*8)*2, wth + (size_t)n*DIN + kn + cc8*8);
                if (lo) cpa16(nwb + (uint32_t)(64*PP + n*PP + cc8*8)*2,
                              wtl + (size_t)n*DIN + kn + cc8*8);
            }
            CP_COMMIT();
        }
        if (c + 2 < NCHUNK) {
            const int kf = (c + 2) * 64;
            #pragma unroll
            for (int i = 0; i < 8; i++)
                xr[i] = *(const float4*)(X + (size_t)(rowblock + xr_ + i*16)*DIN + kf + xc4*4);
        }

        __nv_bfloat16* cXh = cur;
        __nv_bfloat16* cXl = cXh + 128*PP;
        __nv_bfloat16* cWh = cXl + 128*PP;
        __nv_bfloat16* cWl = cWh + 64*PP;
        if (lo) {
            #pragma unroll
            for (int ks = 0; ks < 4; ks++) {
                uint32_t afh[4], afl[4];
                ldsm_x4(afh[0], afh[1], afh[2], afh[3], smem_u32(&cXh[arow*PP + ks*16 + acol]));
                ldsm_x4(afl[0], afl[1], afl[2], afl[3], smem_u32(&cXl[arow*PP + ks*16 + acol]));
                #pragma unroll
                for (int jj = 0; jj < 8; jj += 2) {
                    uint32_t bh0,bh1,bh2,bh3, bl0,bl1,bl2,bl3;
                    ldsm_x4(bh0,bh1,bh2,bh3, smem_u32(&cWh[(jj*8 + brow)*PP + ks*16 + bcol]));
                    ldsm_x4(bl0,bl1,bl2,bl3, smem_u32(&cWl[(jj*8 + brow)*PP + ks*16 + bcol]));
                    mma16816(cacc[jj],   afh, bh0, bh1);
                    mma16816(cacc[jj],   afh, bl0, bl1);
                    mma16816(cacc[jj],   afl, bh0, bh1);
                    mma16816(cacc[jj+1], afh, bh2, bh3);
                    mma16816(cacc[jj+1], afh, bl2, bl3);
                    mma16816(cacc[jj+1], afl, bh2, bh3);
                }
            }
        } else {
            #pragma unroll
            for (int ks = 0; ks < 4; ks++) {
                uint32_t afh[4];
                ldsm_x4(afh[0], afh[1], afh[2], afh[3], smem_u32(&cXh[arow*PP + ks*16 + acol]));
                #pragma unroll
                for (int jj = 0; jj < 8; jj += 2) {
                    uint32_t bh0,bh1,bh2,bh3;
                    ldsm_x4(bh0,bh1,bh2,bh3, smem_u32(&cWh[(jj*8 + brow)*PP + ks*16 + bcol]));
                    mma16816(cacc[jj],   afh, bh0, bh1);
                    mma16816(cacc[jj+1], afh, bh2, bh3);
                }
            }
        }
        CP_WAIT0();
        __syncthreads();
    }

    // ---- epilogue ----
    const int cc = (lane & 3) * 2;
    #pragma unroll
    for (int j = 0; j < 8; j++) {
        float b0 = bias[j*8 + cc], b1 = bias[j*8 + cc + 1];
        cacc[j][0] += b0; cacc[j][1] += b1;
        cacc[j][2] += b0; cacc[j][3] += b1;
    }

    if (which < 2) {
        float ss0 = 0.f, ss1 = 0.f;
        #pragma unroll
        for (int j = 0; j < 8; j++) {
            ss0 += cacc[j][0]*cacc[j][0] + cacc[j][1]*cacc[j][1];
            ss1 += cacc[j][2]*cacc[j][2] + cacc[j][3]*cacc[j][3];
        }
        ss0 += __shfl_xor_sync(0xffffffffu, ss0, 1);
        ss0 += __shfl_xor_sync(0xffffffffu, ss0, 2);
        ss1 += __shfl_xor_sync(0xffffffffu, ss1, 1);
        ss1 += __shfl_xor_sync(0xffffffffu, ss1, 2);
        float sc0 = rsqrtf(ss0), sc1 = rsqrtf(ss1);
        if (which == 0) { sc0 *= 0.125f * LOG2E; sc1 *= 0.125f * LOG2E; }

        __nv_bfloat16* gh = (which == 0) ? g_qh : g_kh;
        const int r0 = rowblock + warp*16 + (lane >> 2);
        const int r1 = r0 + 8;
        #pragma unroll
        for (int j = 0; j < 8; j++) {
            *(uint32_t*)&gh[(size_t)r0*DH + j*8 + cc] = bf2_pack(cacc[j][0]*sc0, cacc[j][1]*sc0);
            *(uint32_t*)&gh[(size_t)r1*DH + j*8 + cc] = bf2_pack(cacc[j][2]*sc1, cacc[j][3]*sc1);
        }
    } else {
        __nv_bfloat16* Th = psm;        // 64 x TP
        __nv_bfloat16* Tl = Th + 64*TP;
        const int r0 = warp*16 + (lane >> 2);
        const int r1 = r0 + 8;
        #pragma unroll
        for (int j = 0; j < 8; j++) {
            #pragma unroll
            for (int e = 0; e < 2; e++) {
                int col = j*8 + cc + e;
                float v0 = cacc[j][e], v1 = cacc[j][2+e];
                __nv_bfloat16 h0 = __float2bfloat16(v0);
                __nv_bfloat16 h1 = __float2bfloat16(v1);
                Th[col*TP + r0] = h0;
                Th[col*TP + r1] = h1;
                Tl[col*TP + r0] = __float2bfloat16(v0 - __bfloat162float(h0));
                Tl[col*TP + r1] = __float2bfloat16(v1 - __bfloat162float(h1));
            }
        }
        __syncthreads();
        const int bb = rowblock >> 11;
        const int s0 = rowblock & (S - 1);
        #pragma unroll
        for (int i = 0; i < 4; i++) {
            int idx = tid + i*256;
            int col = idx >> 4, u = idx & 15;
            size_t g = ((size_t)bb*DH + col)*S + s0 + u*8;
            *(uint4*)&g_vh[g] = *(uint4*)&Th[col*TP + u*8];
            *(uint4*)&g_vl[g] = *(uint4*)&Tl[col*TP + u*8];
        }
        // fused vsum: partial column sums of this 128-row tile (hi+lo), atomic.
        {
            int col = tid & 63, seg = tid >> 6;
            float s = 0.f;
            #pragma unroll 8
            for (int r = seg*32; r < seg*32 + 32; r++)
                s += __bfloat162float(Th[col*TP + r]) + __bfloat162float(Tl[col*TP + r]);
            atomicAdd(&g_vsum[bb*DH + col], s);
        }
    }
}

// ============================================================
// mma.sync flash attention, split-K x2, p = 1+f decomposition,
// cp.async double-buffered K/V. Q smem aliased with V buffer 1 -> 36864 B,
// 5 CTAs/SM. (At the HMMA throughput roofline; unchanged.)
// ============================================================
#define TPITCH 72
#define RB 9216
#define ATTN_SMEM (4 * RB)             // 36864 B

__global__ __launch_bounds__(128, 5) void attn_part_kernel()
{
    extern __shared__ __nv_bfloat16 AS[];

    const int tid = threadIdx.x;
    const int warp = tid >> 5;
    const int lane = tid & 31;
    const int b = blockIdx.y;
    const int q0 = blockIdx.x * 64;
    const int split = blockIdx.z;
    const int key_base = split * KEYS_PER_SPLIT;

    const uint32_t sbase = smem_u32(AS);
    const uint32_t KB[2] = { sbase,        sbase + 2*RB };
    const uint32_t VB[2] = { sbase + RB,   sbase + 3*RB };
    const uint32_t QB = sbase + 3*RB;    // aliases VB[1]; Q consumed before t=0 prefetch

    const __nv_bfloat16* qh_g = g_qh + ((size_t)b*S + q0)*DH;
    const __nv_bfloat16* kh_g = g_kh + (size_t)b*S*DH;
    const __nv_bfloat16* vh_g = g_vh + (size_t)b*DH*S;

    const int sr = tid >> 3;
    const int sc = tid & 7;

    #pragma unroll
    for (int i = 0; i < 4; i++) {
        int r = sr + i*16;
        uint32_t so = (uint32_t)(r*TPITCH + sc*8)*2;
        cpa16(QB + so, qh_g + (size_t)r*DH + sc*8);
        cpa16(KB[0] + so, kh_g + (size_t)(key_base + r)*DH + sc*8);
        cpa16(VB[0] + so, vh_g + (size_t)r*S + key_base + sc*8);
    }
    CP_COMMIT();
    CP_WAIT0();
    __syncthreads();

    const int arow = warp*16 + (lane & 15);
    const int acol = (lane >> 4) * 8;
    const int brow = (lane & 7) | ((lane & 16) >> 1);
    const int bcol = (lane & 8);

    uint32_t qfh[4][4];
    #pragma unroll
    for (int k = 0; k < 4; k++)
        ldsm_x4(qfh[k][0], qfh[k][1], qfh[k][2], qfh[k][3],
                QB + (uint32_t)(arow*TPITCH + k*16 + acol)*2);
    __syncthreads();   // all warps done reading Q before t=0 prefetch reuses QB

    float oacc[8][4];
    #pragma unroll
    for (int j = 0; j < 8; j++)
        #pragma unroll
        for (int i = 0; i < 4; i++) oacc[j][i] = 0.f;
    float lsum0 = 0.f, lsum1 = 0.f;

    for (int t = 0; t < NT; t++) {
        const uint32_t kb = KB[t & 1], vb = VB[t & 1];

        if (t + 1 < NT) {
            const int kn = key_base + (t + 1) * 64;
            const uint32_t nk = KB[(t + 1) & 1], nv = VB[(t + 1) & 1];
            #pragma unroll
            for (int i = 0; i < 4; i++) {
                int r = sr + i*16;
                uint32_t so = (uint32_t)(r*TPITCH + sc*8)*2;
                cpa16(nk + so, kh_g + (size_t)(kn + r)*DH + sc*8);
                cpa16(nv + so, vh_g + (size_t)r*S + kn + sc*8);
            }
            CP_COMMIT();
        }

        float sacc[8][4];
        #pragma unroll
        for (int j = 0; j < 8; j++)
            #pragma unroll
            for (int i = 0; i < 4; i++) sacc[j][i] = 0.f;

        #pragma unroll
        for (int k = 0; k < 4; k++) {
            #pragma unroll
            for (int jj = 0; jj < 8; jj += 2) {
                uint32_t bh0,bh1,bh2,bh3;
                ldsm_x4(bh0,bh1,bh2,bh3, kb + (uint32_t)((jj*8 + brow)*TPITCH + k*16 + bcol)*2);
                mma16816(sacc[jj],   qfh[k], bh0, bh1);
                mma16816(sacc[jj+1], qfh[k], bh2, bh3);
            }
        }

        #pragma unroll
        for (int kk = 0; kk < 4; kk++) {
            uint32_t pf[4];
            {
                float f0 = ex2f(sacc[2*kk][0])   - 1.0f;
                float f1 = ex2f(sacc[2*kk][1])   - 1.0f;
                float f2 = ex2f(sacc[2*kk][2])   - 1.0f;
                float f3 = ex2f(sacc[2*kk][3])   - 1.0f;
                float f4 = ex2f(sacc[2*kk+1][0]) - 1.0f;
                float f5 = ex2f(sacc[2*kk+1][1]) - 1.0f;
                float f6 = ex2f(sacc[2*kk+1][2]) - 1.0f;
                float f7 = ex2f(sacc[2*kk+1][3]) - 1.0f;
                lsum0 += f0 + f1 + f4 + f5;
                lsum1 += f2 + f3 + f6 + f7;
                pf[0] = bf2_pack(f0, f1);
                pf[1] = bf2_pack(f2, f3);
                pf[2] = bf2_pack(f4, f5);
                pf[3] = bf2_pack(f6, f7);
            }
            #pragma unroll
            for (int jj = 0; jj < 8; jj += 2) {
                uint32_t vh0,vh1,vh2,vh3;
                ldsm_x4(vh0,vh1,vh2,vh3, vb + (uint32_t)((jj*8 + brow)*TPITCH + kk*16 + bcol)*2);
                mma16816(oacc[jj],   pf, vh0, vh1);
                mma16816(oacc[jj+1], pf, vh2, vh3);
            }
        }

        if (t + 1 < NT) {
            CP_WAIT0();
            __syncthreads();
        }
    }

    lsum0 += __shfl_xor_sync(0xffffffffu, lsum0, 1);
    lsum0 += __shfl_xor_sync(0xffffffffu, lsum0, 2);
    lsum1 += __shfl_xor_sync(0xffffffffu, lsum1, 1);
    lsum1 += __shfl_xor_sync(0xffffffffu, lsum1, 2);

    const size_t grow = (size_t)b*S + q0 + warp*16 + (lane >> 2);
    const int cc = (lane & 3) * 2;
    float* o0 = g_opart + ((size_t)split*NROWS + grow)*DH + cc;
    float* o1 = o0 + 8*DH;
    #pragma unroll
    for (int j = 0; j < 8; j++) {
        *(float2*)(o0 + j*8) = make_float2(oacc[j][0], oacc[j][1]);
        *(float2*)(o1 + j*8) = make_float2(oacc[j][2], oacc[j][3]);
    }
    if ((lane & 3) == 0) {
        g_lpart[(size_t)split*NROWS + grow]     = lsum0;
        g_lpart[(size_t)split*NROWS + grow + 8] = lsum1;
    }
}

// ============================================================
// Combine: o = (vsum + Sum_splits f*vh) / (2048 + Sum_splits Sum f).
// ============================================================
__global__ __launch_bounds__(256) void attn_combine_kernel(float* __restrict__ out)
{
    const int id  = blockIdx.x * 256 + threadIdx.x;
    const int row = id >> 4;
    const int c   = id & 15;

    float4 acc = *(const float4*)&g_vsum[(row >> 11)*DH + c*4];
    float L = (float)S;
    #pragma unroll
    for (int s = 0; s < KSPLIT; s++) {
        const float4 v = ((const float4*)(g_opart + ((size_t)s*NROWS + row)*DH))[c];
        acc.x += v.x; acc.y += v.y; acc.z += v.z; acc.w += v.w;
        L += g_lpart[(size_t)s*NROWS + row];
    }
    const float inv = 1.0f / L;
    ((float4*)out)[id] = make_float4(acc.x*inv, acc.y*inv, acc.z*inv, acc.w*inv);
}

// ============================================================
extern "C" void kernel_launch(void* const* d_in, const int* in_sizes, int n_in,
                              void* d_out, int out_size)
{
    const float* query = (const float*)d_in[0];
    const float* key   = (const float*)d_in[1];
    const float* value = (const float*)d_in[2];
    const float* Wq    = (const float*)d_in[3];
    const float* bq    = (const float*)d_in[4];
    const float* Wk    = (const float*)d_in[5];
    const float* bk    = (const float*)d_in[6];
    const float* Wv    = (const float*)d_in[7];
    const float* bv    = (const float*)d_in[8];
    float* out = (float*)d_out;

    cudaFuncSetAttribute(proj_kernel,
                         cudaFuncAttributeMaxDynamicSharedMemorySize, PROJ_SMEM);
    cudaFuncSetAttribute(attn_part_kernel,
                         cudaFuncAttributeMaxDynamicSharedMemorySize, ATTN_SMEM);

    prep_w<<<3*DIN*DH/256, 256>>>(Wq, Wk, Wv);

    dim3 pgrid(NROWS / 128, 3);   // y=0 -> V first (long CTAs), then Q, K
    proj_kernel<<<pgrid, 256, PROJ_SMEM>>>(query, key, value, bq, bk, bv);

    dim3 agrid(S / 64, B, KSPLIT);    // 32 x 8 x 2 = 512 CTAs
    attn_part_kernel<<<agrid, 128, ATTN_SMEM>>>();

    attn_combine_kernel<<<NROWS * 16 / 256, 256>>>(out);
}

// round 17
// speedup vs baseline: 1.1376x; 1.0003x over previous
#include <cuda_runtime.h>
#include <cuda_bf16.h>
#include <cstdint>

// Problem constants
#define B 8
#define S 2048
#define DIN 768
#define DH 64
#define NROWS (B*S)      // 16384
#define KSPLIT 2
#define KEYS_PER_SPLIT (S/KSPLIT)   // 1024
#define NT (KEYS_PER_SPLIT/64)      // 16 tiles per CTA

// q/k: pure bf16 (hi only), pure-bf16 GEMM (score noise ~3e-5, validated).
// q rows pre-scaled by 0.125*log2(e) -> QK MMA yields log2-domain scores.
// v: bf16 hi/lo computed bf16x3 (v errors propagate directly).
// Attention: p = 1 + f decomposition, O = Sum(v) + Sum(f*vh), f = 2^s - 1.
// Split-K partials stored as bf16 (partial rms ~0.2 -> storage err ~1e-5 rel).
__device__ __nv_bfloat16 g_qh[NROWS*DH];                   // [b*S+s][d]
__device__ __nv_bfloat16 g_kh[NROWS*DH];                   // [b*S+s][d]
__device__ __nv_bfloat16 g_vh[B*DH*S],  g_vl[B*DH*S];      // TRANSPOSED [b][d][s]
__device__ __nv_bfloat16 g_wth[3*DH*DIN], g_wtl[3*DH*DIN]; // [which][n][k] hi/lo
__device__ float g_vsum[B*DH];
__device__ __nv_bfloat16 g_opart[KSPLIT*NROWS*DH];   // 4.2 MB (bf16 partials)
__device__ float g_lpart[KSPLIT*NROWS];

#define LOG2E 1.4426950408889634f

__device__ __forceinline__ uint32_t smem_u32(const void* p) {
    uint32_t a;
    asm("{ .reg .u64 t; cvta.to.shared.u64 t, %1; cvt.u32.u64 %0, t; }" : "=r"(a) : "l"(p));
    return a;
}

// ---- base-PTX tensor core / async ops (sm_80+, compile for plain sm_103) ----
__device__ __forceinline__ void ldsm_x4(uint32_t &r0, uint32_t &r1, uint32_t &r2, uint32_t &r3,
                                        uint32_t addr) {
    asm volatile("ldmatrix.sync.aligned.m8n8.x4.shared.b16 {%0,%1,%2,%3}, [%4];"
                 : "=r"(r0), "=r"(r1), "=r"(r2), "=r"(r3) : "r"(addr));
}
__device__ __forceinline__ void mma16816(float* c, const uint32_t* a, uint32_t b0, uint32_t b1) {
    asm volatile("mma.sync.aligned.m16n8k16.row.col.f32.bf16.bf16.f32 "
                 "{%0,%1,%2,%3}, {%4,%5,%6,%7}, {%8,%9}, {%0,%1,%2,%3};"
                 : "+f"(c[0]), "+f"(c[1]), "+f"(c[2]), "+f"(c[3])
                 : "r"(a[0]), "r"(a[1]), "r"(a[2]), "r"(a[3]), "r"(b0), "r"(b1));
}
__device__ __forceinline__ void cpa16(uint32_t dst, const void* src) {
    asm volatile("cp.async.cg.shared.global [%0], [%1], 16;" :: "r"(dst), "l"(src));
}
#define CP_COMMIT() asm volatile("cp.async.commit_group;" ::: "memory")
#define CP_WAIT0()  asm volatile("cp.async.wait_group 0;" ::: "memory")

__device__ __forceinline__ float ex2f(float x) {
    float r; asm("ex2.approx.f32 %0, %1;" : "=f"(r) : "f"(x)); return r;
}
__device__ __forceinline__ uint32_t bf2_pack(float a, float b) {
    uint32_t r;
    asm("cvt.rn.bf16x2.f32 %0, %1, %2;" : "=r"(r) : "f"(b), "f"(a));
    return r;
}
__device__ __forceinline__ void split2(float a, float b, uint32_t &hp, uint32_t &lp) {
    __nv_bfloat16 ha = __float2bfloat16(a), hb = __float2bfloat16(b);
    float la = a - __bfloat162float(ha), lb = b - __bfloat162float(hb);
    __nv_bfloat162 hh = __halves2bfloat162(ha, hb);
    hp = *(uint32_t*)&hh;
    lp = bf2_pack(la, lb);
}

// ============================================================
// prep_w: transpose + bf16 hi/lo split of the 3 weight matrices once.
// Block 0 also zeroes g_vsum (accumulated by proj's v epilogue via atomics).
// ============================================================
__global__ __launch_bounds__(256) void prep_w(
    const float* __restrict__ Wq, const float* __restrict__ Wk, const float* __restrict__ Wv)
{
    if (blockIdx.x == 0) {
        g_vsum[threadIdx.x] = 0.f;
        g_vsum[threadIdx.x + 256] = 0.f;
    }
    int idx = blockIdx.x * 256 + threadIdx.x;
    int which = idx / (DIN*DH);
    int rem = idx - which * (DIN*DH);
    int k = rem >> 6;
    int n = rem & 63;
    const float* W = (which == 0) ? Wq : (which == 1) ? Wk : Wv;
    float w = W[(size_t)k*DH + n];
    __nv_bfloat16 h = __float2bfloat16(w);
    __nv_bfloat16 l = __float2bfloat16(w - __bfloat162float(h));
    size_t o = ((size_t)which*DH + n)*DIN + k;
    g_wth[o] = h;
    g_wtl[o] = l;
}

// ============================================================
// Projection, double-buffered cp.async pipeline.
// WAVE ORDERING: blockIdx.y = 0 -> V (long, bf16x3), 1 -> Q, 2 -> K.
// q/k: pure bf16 (1 MMA/slot). v: bf16x3 + fused vsum.
// ============================================================
#define PP 72
#define TP 136
#define NCHUNK (DIN/64)                         // 12
#define STAGE_HALVES (2*128*PP + 2*64*PP)
#define PROJ_SMEM (2 * STAGE_HALVES * 2)        // 110592 B

__global__ __launch_bounds__(256, 2) void proj_kernel(
    const float* __restrict__ Xq, const float* __restrict__ Xk, const float* __restrict__ Xv,
    const float* __restrict__ bq, const float* __restrict__ bk, const float* __restrict__ bv)
{
    extern __shared__ __nv_bfloat16 psm[];

    // y=0 -> v (which=2), y=1 -> q (which=0), y=2 -> k (which=1)
    const int which = (blockIdx.y == 0) ? 2 : (int)blockIdx.y - 1;
    const bool lo = (which == 2);        // uniform per CTA
    const float* X; const float* bias;
    if (which == 0)      { X = Xq; bias = bq; }
    else if (which == 1) { X = Xk; bias = bk; }
    else                 { X = Xv; bias = bv; }
    const __nv_bfloat16* wth = g_wth + (size_t)which*DH*DIN;
    const __nv_bfloat16* wtl = g_wtl + (size_t)which*DH*DIN;

    const int tid = threadIdx.x;
    const int warp = tid >> 5;
    const int lane = tid & 31;
    const int rowblock = blockIdx.x * 128;

    float cacc[8][4];
    #pragma unroll
    for (int j = 0; j < 8; j++)
        #pragma unroll
        for (int i = 0; i < 4; i++) cacc[j][i] = 0.f;

    const int arow = warp*16 + (lane & 15);
    const int acol = (lane >> 4) * 8;
    const int brow = (lane & 7) | ((lane & 16) >> 1);
    const int bcol = (lane & 8);

    const int xr_ = tid >> 4;
    const int xc4 = tid & 15;
    float4 xr[8];

    // ---- prologue: chunk 0 stage + chunk 1 LDG ----
    #pragma unroll
    for (int i = 0; i < 8; i++)
        xr[i] = *(const float4*)(X + (size_t)(rowblock + xr_ + i*16)*DIN + xc4*4);
    {
        __nv_bfloat16* sXh = psm;
        __nv_bfloat16* sXl = sXh + 128*PP;
        uint32_t whb = smem_u32(sXl + 128*PP);
        #pragma unroll
        for (int i = 0; i < 8; i++) {
            int r = xr_ + i*16;
            if (lo) {
                uint32_t h0, l0, h1, l1;
                split2(xr[i].x, xr[i].y, h0, l0);
                split2(xr[i].z, xr[i].w, h1, l1);
                *(uint2*)&sXh[r*PP + xc4*4] = make_uint2(h0, h1);
                *(uint2*)&sXl[r*PP + xc4*4] = make_uint2(l0, l1);
            } else {
                *(uint2*)&sXh[r*PP + xc4*4] =
                    make_uint2(bf2_pack(xr[i].x, xr[i].y), bf2_pack(xr[i].z, xr[i].w));
            }
        }
        #pragma unroll
        for (int i = 0; i < 2; i++) {
            int idx = tid + i*256;
            int n = idx >> 3, c = idx & 7;
            cpa16(whb + (uint32_t)(n*PP + c*8)*2, wth + (size_t)n*DIN + c*8);
            if (lo) cpa16(whb + (uint32_t)(64*PP + n*PP + c*8)*2, wtl + (size_t)n*DIN + c*8);
        }
        CP_COMMIT();
    }
    #pragma unroll
    for (int i = 0; i < 8; i++)
        xr[i] = *(const float4*)(X + (size_t)(rowblock + xr_ + i*16)*DIN + 64 + xc4*4);
    CP_WAIT0();
    __syncthreads();

    // ---- main loop: one sync per chunk ----
    for (int c = 0; c < NCHUNK; c++) {
        __nv_bfloat16* cur = psm + (c & 1) * STAGE_HALVES;
        __nv_bfloat16* nxt = psm + ((c + 1) & 1) * STAGE_HALVES;

        if (c + 1 < NCHUNK) {
            __nv_bfloat16* nXh = nxt;
            __nv_bfloat16* nXl = nXh + 128*PP;
            uint32_t nwb = smem_u32(nXl + 128*PP);
            const int kn = (c + 1) * 64;
            #pragma unroll
            for (int i = 0; i < 8; i++) {
                int r = xr_ + i*16;
                if (lo) {
                    uint32_t h0, l0, h1, l1;
                    split2(xr[i].x, xr[i].y, h0, l0);
                    split2(xr[i].z, xr[i].w, h1, l1);
                    *(uint2*)&nXh[r*PP + xc4*4] = make_uint2(h0, h1);
                    *(uint2*)&nXl[r*PP + xc4*4] = make_uint2(l0, l1);
                } else {
                    *(uint2*)&nXh[r*PP + xc4*4] =
                        make_uint2(bf2_pack(xr[i].x, xr[i].y), bf2_pack(xr[i].z, xr[i].w));
                }
            }
            #pragma unroll
            for (int i = 0; i < 2; i++) {
                int idx = tid + i*256;
                int n = idx >> 3, cc8 = idx & 7;
                cpa16(nwb + (uint32_t)(n*PP + cc8*8)*2, wth + (size_t)n*DIN + kn + cc8*8);
                if (lo) cpa16(nwb + (uint32_t)(64*PP + n*PP + cc8*8)*2,
                              wtl + (size_t)n*DIN + kn + cc8*8);
            }
            CP_COMMIT();
        }
        if (c + 2 < NCHUNK) {
            const int kf = (c + 2) * 64;
            #pragma unroll
            for (int i = 0; i < 8; i++)
                xr[i] = *(const float4*)(X + (size_t)(rowblock + xr_ + i*16)*DIN + kf + xc4*4);
        }

        __nv_bfloat16* cXh = cur;
        __nv_bfloat16* cXl = cXh + 128*PP;
        __nv_bfloat16* cWh = cXl + 128*PP;
        __nv_bfloat16* cWl = cWh + 64*PP;
        if (lo) {
            #pragma unroll
            for (int ks = 0; ks < 4; ks++) {
                uint32_t afh[4], afl[4];
                ldsm_x4(afh[0], afh[1], afh[2], afh[3], smem_u32(&cXh[arow*PP + ks*16 + acol]));
                ldsm_x4(afl[0], afl[1], afl[2], afl[3], smem_u32(&cXl[arow*PP + ks*16 + acol]));
                #pragma unroll
                for (int jj = 0; jj < 8; jj += 2) {
                    uint32_t bh0,bh1,bh2,bh3, bl0,bl1,bl2,bl3;
                    ldsm_x4(bh0,bh1,bh2,bh3, smem_u32(&cWh[(jj*8 + brow)*PP + ks*16 + bcol]));
                    ldsm_x4(bl0,bl1,bl2,bl3, smem_u32(&cWl[(jj*8 + brow)*PP + ks*16 + bcol]));
                    mma16816(cacc[jj],   afh, bh0, bh1);
                    mma16816(cacc[jj],   afh, bl0, bl1);
                    mma16816(cacc[jj],   afl, bh0, bh1);
                    mma16816(cacc[jj+1], afh, bh2, bh3);
                    mma16816(cacc[jj+1], afh, bl2, bl3);
                    mma16816(cacc[jj+1], afl, bh2, bh3);
                }
            }
        } else {
            #pragma unroll
            for (int ks = 0; ks < 4; ks++) {
                uint32_t afh[4];
                ldsm_x4(afh[0], afh[1], afh[2], afh[3], smem_u32(&cXh[arow*PP + ks*16 + acol]));
                #pragma unroll
                for (int jj = 0; jj < 8; jj += 2) {
                    uint32_t bh0,bh1,bh2,bh3;
                    ldsm_x4(bh0,bh1,bh2,bh3, smem_u32(&cWh[(jj*8 + brow)*PP + ks*16 + bcol]));
                    mma16816(cacc[jj],   afh, bh0, bh1);
                    mma16816(cacc[jj+1], afh, bh2, bh3);
                }
            }
        }
        CP_WAIT0();
        __syncthreads();
    }

    // ---- epilogue ----
    const int cc = (lane & 3) * 2;
    #pragma unroll
    for (int j = 0; j < 8; j++) {
        float b0 = bias[j*8 + cc], b1 = bias[j*8 + cc + 1];
        cacc[j][0] += b0; cacc[j][1] += b1;
        cacc[j][2] += b0; cacc[j][3] += b1;
    }

    if (which < 2) {
        float ss0 = 0.f, ss1 = 0.f;
        #pragma unroll
        for (int j = 0; j < 8; j++) {
            ss0 += cacc[j][0]*cacc[j][0] + cacc[j][1]*cacc[j][1];
            ss1 += cacc[j][2]*cacc[j][2] + cacc[j][3]*cacc[j][3];
        }
        ss0 += __shfl_xor_sync(0xffffffffu, ss0, 1);
        ss0 += __shfl_xor_sync(0xffffffffu, ss0, 2);
        ss1 += __shfl_xor_sync(0xffffffffu, ss1, 1);
        ss1 += __shfl_xor_sync(0xffffffffu, ss1, 2);
        float sc0 = rsqrtf(ss0), sc1 = rsqrtf(ss1);
        if (which == 0) { sc0 *= 0.125f * LOG2E; sc1 *= 0.125f * LOG2E; }

        __nv_bfloat16* gh = (which == 0) ? g_qh : g_kh;
        const int r0 = rowblock + warp*16 + (lane >> 2);
        const int r1 = r0 + 8;
        #pragma unroll
        for (int j = 0; j < 8; j++) {
            *(uint32_t*)&gh[(size_t)r0*DH + j*8 + cc] = bf2_pack(cacc[j][0]*sc0, cacc[j][1]*sc0);
            *(uint32_t*)&gh[(size_t)r1*DH + j*8 + cc] = bf2_pack(cacc[j][2]*sc1, cacc[j][3]*sc1);
        }
    } else {
        __nv_bfloat16* Th = psm;        // 64 x TP
        __nv_bfloat16* Tl = Th + 64*TP;
        const int r0 = warp*16 + (lane >> 2);
        const int r1 = r0 + 8;
        #pragma unroll
        for (int j = 0; j < 8; j++) {
            #pragma unroll
            for (int e = 0; e < 2; e++) {
                int col = j*8 + cc + e;
                float v0 = cacc[j][e], v1 = cacc[j][2+e];
                __nv_bfloat16 h0 = __float2bfloat16(v0);
                __nv_bfloat16 h1 = __float2bfloat16(v1);
                Th[col*TP + r0] = h0;
                Th[col*TP + r1] = h1;
                Tl[col*TP + r0] = __float2bfloat16(v0 - __bfloat162float(h0));
                Tl[col*TP + r1] = __float2bfloat16(v1 - __bfloat162float(h1));
            }
        }
        __syncthreads();
        const int bb = rowblock >> 11;
        const int s0 = rowblock & (S - 1);
        #pragma unroll
        for (int i = 0; i < 4; i++) {
            int idx = tid + i*256;
            int col = idx >> 4, u = idx & 15;
            size_t g = ((size_t)bb*DH + col)*S + s0 + u*8;
            *(uint4*)&g_vh[g] = *(uint4*)&Th[col*TP + u*8];
            *(uint4*)&g_vl[g] = *(uint4*)&Tl[col*TP + u*8];
        }
        // fused vsum: partial column sums of this 128-row tile (hi+lo), atomic.
        {
            int col = tid & 63, seg = tid >> 6;
            float s = 0.f;
            #pragma unroll 8
            for (int r = seg*32; r < seg*32 + 32; r++)
                s += __bfloat162float(Th[col*TP + r]) + __bfloat162float(Tl[col*TP + r]);
            atomicAdd(&g_vsum[bb*DH + col], s);
        }
    }
}

// ============================================================
// mma.sync flash attention, split-K x2, p = 1+f decomposition,
// cp.async double-buffered K/V. Q smem aliased with V buffer 1 -> 36864 B,
// 5 CTAs/SM. Partials stored as bf16 (packed pairs).
// ============================================================
#define TPITCH 72
#define RB 9216
#define ATTN_SMEM (4 * RB)             // 36864 B

__global__ __launch_bounds__(128, 5) void attn_part_kernel()
{
    extern __shared__ __nv_bfloat16 AS[];

    const int tid = threadIdx.x;
    const int warp = tid >> 5;
    const int lane = tid & 31;
    const int b = blockIdx.y;
    const int q0 = blockIdx.x * 64;
    const int split = blockIdx.z;
    const int key_base = split * KEYS_PER_SPLIT;

    const uint32_t sbase = smem_u32(AS);
    const uint32_t KB[2] = { sbase,        sbase + 2*RB };
    const uint32_t VB[2] = { sbase + RB,   sbase + 3*RB };
    const uint32_t QB = sbase + 3*RB;    // aliases VB[1]; Q consumed before t=0 prefetch

    const __nv_bfloat16* qh_g = g_qh + ((size_t)b*S + q0)*DH;
    const __nv_bfloat16* kh_g = g_kh + (size_t)b*S*DH;
    const __nv_bfloat16* vh_g = g_vh + (size_t)b*DH*S;

    const int sr = tid >> 3;
    const int sc = tid & 7;

    #pragma unroll
    for (int i = 0; i < 4; i++) {
        int r = sr + i*16;
        uint32_t so = (uint32_t)(r*TPITCH + sc*8)*2;
        cpa16(QB + so, qh_g + (size_t)r*DH + sc*8);
        cpa16(KB[0] + so, kh_g + (size_t)(key_base + r)*DH + sc*8);
        cpa16(VB[0] + so, vh_g + (size_t)r*S + key_base + sc*8);
    }
    CP_COMMIT();
    CP_WAIT0();
    __syncthreads();

    const int arow = warp*16 + (lane & 15);
    const int acol = (lane >> 4) * 8;
    const int brow = (lane & 7) | ((lane & 16) >> 1);
    const int bcol = (lane & 8);

    uint32_t qfh[4][4];
    #pragma unroll
    for (int k = 0; k < 4; k++)
        ldsm_x4(qfh[k][0], qfh[k][1], qfh[k][2], qfh[k][3],
                QB + (uint32_t)(arow*TPITCH + k*16 + acol)*2);
    __syncthreads();   // all warps done reading Q before t=0 prefetch reuses QB

    float oacc[8][4];
    #pragma unroll
    for (int j = 0; j < 8; j++)
        #pragma unroll
        for (int i = 0; i < 4; i++) oacc[j][i] = 0.f;
    float lsum0 = 0.f, lsum1 = 0.f;

    for (int t = 0; t < NT; t++) {
        const uint32_t kb = KB[t & 1], vb = VB[t & 1];

        if (t + 1 < NT) {
            const int kn = key_base + (t + 1) * 64;
            const uint32_t nk = KB[(t + 1) & 1], nv = VB[(t + 1) & 1];
            #pragma unroll
            for (int i = 0; i < 4; i++) {
                int r = sr + i*16;
                uint32_t so = (uint32_t)(r*TPITCH + sc*8)*2;
                cpa16(nk + so, kh_g + (size_t)(kn + r)*DH + sc*8);
                cpa16(nv + so, vh_g + (size_t)r*S + kn + sc*8);
            }
            CP_COMMIT();
        }

        float sacc[8][4];
        #pragma unroll
        for (int j = 0; j < 8; j++)
            #pragma unroll
            for (int i = 0; i < 4; i++) sacc[j][i] = 0.f;

        #pragma unroll
        for (int k = 0; k < 4; k++) {
            #pragma unroll
            for (int jj = 0; jj < 8; jj += 2) {
                uint32_t bh0,bh1,bh2,bh3;
                ldsm_x4(bh0,bh1,bh2,bh3, kb + (uint32_t)((jj*8 + brow)*TPITCH + k*16 + bcol)*2);
                mma16816(sacc[jj],   qfh[k], bh0, bh1);
                mma16816(sacc[jj+1], qfh[k], bh2, bh3);
            }
        }

        #pragma unroll
        for (int kk = 0; kk < 4; kk++) {
            uint32_t pf[4];
            {
                float f0 = ex2f(sacc[2*kk][0])   - 1.0f;
                float f1 = ex2f(sacc[2*kk][1])   - 1.0f;
                float f2 = ex2f(sacc[2*kk][2])   - 1.0f;
                float f3 = ex2f(sacc[2*kk][3])   - 1.0f;
                float f4 = ex2f(sacc[2*kk+1][0]) - 1.0f;
                float f5 = ex2f(sacc[2*kk+1][1]) - 1.0f;
                float f6 = ex2f(sacc[2*kk+1][2]) - 1.0f;
                float f7 = ex2f(sacc[2*kk+1][3]) - 1.0f;
                lsum0 += f0 + f1 + f4 + f5;
                lsum1 += f2 + f3 + f6 + f7;
                pf[0] = bf2_pack(f0, f1);
                pf[1] = bf2_pack(f2, f3);
                pf[2] = bf2_pack(f4, f5);
                pf[3] = bf2_pack(f6, f7);
            }
            #pragma unroll
            for (int jj = 0; jj < 8; jj += 2) {
                uint32_t vh0,vh1,vh2,vh3;
                ldsm_x4(vh0,vh1,vh2,vh3, vb + (uint32_t)((jj*8 + brow)*TPITCH + kk*16 + bcol)*2);
                mma16816(oacc[jj],   pf, vh0, vh1);
                mma16816(oacc[jj+1], pf, vh2, vh3);
            }
        }

        if (t + 1 < NT) {
            CP_WAIT0();
            __syncthreads();
        }
    }

    lsum0 += __shfl_xor_sync(0xffffffffu, lsum0, 1);
    lsum0 += __shfl_xor_sync(0xffffffffu, lsum0, 2);
    lsum1 += __shfl_xor_sync(0xffffffffu, lsum1, 1);
    lsum1 += __shfl_xor_sync(0xffffffffu, lsum1, 2);

    const size_t grow = (size_t)b*S + q0 + warp*16 + (lane >> 2);
    const int cc = (lane & 3) * 2;
    __nv_bfloat16* o0 = g_opart + ((size_t)split*NROWS + grow)*DH + cc;
    __nv_bfloat16* o1 = o0 + 8*DH;
    #pragma unroll
    for (int j = 0; j < 8; j++) {
        *(uint32_t*)(o0 + j*8) = bf2_pack(oacc[j][0], oacc[j][1]);
        *(uint32_t*)(o1 + j*8) = bf2_pack(oacc[j][2], oacc[j][3]);
    }
    if ((lane & 3) == 0) {
        g_lpart[(size_t)split*NROWS + grow]     = lsum0;
        g_lpart[(size_t)split*NROWS + grow + 8] = lsum1;
    }
}

// ============================================================
// Combine: o = (vsum + Sum_splits f*vh) / (2048 + Sum_splits Sum f).
// Partials are bf16-packed: uint2 load = 4 columns.
// ============================================================
__global__ __launch_bounds__(256) void attn_combine_kernel(float* __restrict__ out)
{
    const int id  = blockIdx.x * 256 + threadIdx.x;
    const int row = id >> 4;
    const int c   = id & 15;

    float4 acc = *(const float4*)&g_vsum[(row >> 11)*DH + c*4];
    float L = (float)S;
    #pragma unroll
    for (int s = 0; s < KSPLIT; s++) {
        uint2 pv = *(const uint2*)&g_opart[((size_t)s*NROWS + row)*DH + c*4];
        float2 a = __bfloat1622float2(*(const __nv_bfloat162*)&pv.x);
        float2 bq = __bfloat1622float2(*(const __nv_bfloat162*)&pv.y);
        acc.x += a.x; acc.y += a.y; acc.z += bq.x; acc.w += bq.y;
        L += g_lpart[(size_t)s*NROWS + row];
    }
    const float inv = 1.0f / L;
    ((float4*)out)[id] = make_float4(acc.x*inv, acc.y*inv, acc.z*inv, acc.w*inv);
}

// ============================================================
extern "C" void kernel_launch(void* const* d_in, const int* in_sizes, int n_in,
                              void* d_out, int out_size)
{
    const float* query = (const float*)d_in[0];
    const float* key   = (const float*)d_in[1];
    const float* value = (const float*)d_in[2];
    const float* Wq    = (const float*)d_in[3];
    const float* bq    = (const float*)d_in[4];
    const float* Wk    = (const float*)d_in[5];
    const float* bk    = (const float*)d_in[6];
    const float* Wv    = (const float*)d_in[7];
    const float* bv    = (const float*)d_in[8];
    float* out = (float*)d_out;

    cudaFuncSetAttribute(proj_kernel,
                         cudaFuncAttributeMaxDynamicSharedMemorySize, PROJ_SMEM);
    cudaFuncSetAttribute(attn_part_kernel,
                         cudaFuncAttributeMaxDynamicSharedMemorySize, ATTN_SMEM);

    prep_w<<<3*DIN*DH/256, 256>>>(Wq, Wk, Wv);

    dim3 pgrid(NROWS / 128, 3);   // y=0 -> V first (long CTAs), then Q, K
    proj_kernel<<<pgrid, 256, PROJ_SMEM>>>(query, key, value, bq, bk, bv);

    dim3 agrid(S / 64, B, KSPLIT);    // 32 x 8 x 2 = 512 CTAs
    attn_part_kernel<<<agrid, 128, ATTN_SMEM>>>();

    attn_combine_kernel<<<NROWS * 16 / 256, 256>>>(out);
}